// round 11
// baseline (speedup 1.0000x reference)
#include <cuda_runtime.h>
#include <cuda_fp16.h>
#include <cstdint>

#define L_    128
#define J_    24
#define NPIX  112
#define I_    14
#define KH_   9
#define KO_   24
#define MT    8
#define NTH   448
#define NKQ   240            // K' = 10 taps * 24 j
#define XW    1452           // xs words per ms slice: 121 cols * 12 half2-words

// Precomputed combined weights (prologue output)
__device__ uint32_t g_Ch[(NKQ / 2) * KO_];   // half2 {C[2q][k], C[2q+1][k]}
__device__ float    g_A1[KO_ * KH_ * J_];    // fp32 [k][kh][j] (n==0 wrap fix)

// dynamic smem offsets (bytes)
#define OFF_XS    0
#define OFF_CS    (MT * XW * 4)              // 46464
#define OFF_XEDGE (OFF_CS + (NKQ/2)*KO_*4)   // 57984
#define OFF_CORRP (OFF_XEDGE + MT*J_*9*4)    // 64896
#define OFF_CORR  (OFF_CORRP + MT*KO_*KH_*4) // 71808
#define SMEM_SZ   (OFF_CORR + MT*KO_*4)      // 72576

__device__ __forceinline__ void mma_f16(float* d, const uint32_t* a, const uint32_t* b) {
    asm volatile(
        "mma.sync.aligned.m16n8k16.row.col.f32.f16.f16.f32 "
        "{%0,%1,%2,%3}, {%4,%5,%6,%7}, {%8,%9}, {%0,%1,%2,%3};"
        : "+f"(d[0]), "+f"(d[1]), "+f"(d[2]), "+f"(d[3])
        : "r"(a[0]), "r"(a[1]), "r"(a[2]), "r"(a[3]), "r"(b[0]), "r"(b[1]));
}

__device__ __forceinline__ float cval(const float* __restrict__ w1,
                                      const float* __restrict__ w2,
                                      int kq, int k) {
    int t10 = kq / J_, j = kq % J_;
    float c = 0.0f;
    if (t10 >= 1) {
        int kh = t10 - 1;
        #pragma unroll
        for (int i = 0; i < I_; i++)
            c = fmaf(w2[(j * 2 + 0) * I_ + i], w1[(k * KH_ + kh) * I_ + i], c);
    }
    if (t10 <= 8) {
        int kh = t10;
        #pragma unroll
        for (int i = 0; i < I_; i++)
            c = fmaf(w2[(j * 2 + 1) * I_ + i], w1[(k * KH_ + kh) * I_ + i], c);
    }
    return c;
}

__global__ void prologue_kernel(const float* __restrict__ w1,
                                const float* __restrict__ w2) {
    int idx = blockIdx.x * blockDim.x + threadIdx.x;
    if (idx < (NKQ / 2) * KO_) {
        int kq2 = idx / KO_, k = idx % KO_;
        float c0 = cval(w1, w2, 2 * kq2, k);
        float c1 = cval(w1, w2, 2 * kq2 + 1, k);
        __half2 h = __floats2half2_rn(c0, c1);   // low = even kq
        g_Ch[idx] = *(uint32_t*)&h;
    } else if (idx < (NKQ / 2) * KO_ + KO_ * KH_ * J_) {
        int r = idx - (NKQ / 2) * KO_;
        int k = r / (KH_ * J_);
        int rem = r % (KH_ * J_);
        int kh = rem / J_, j = rem % J_;
        float s = 0.0f;
        #pragma unroll
        for (int i = 0; i < I_; i++)
            s = fmaf(w2[(j * 2 + 1) * I_ + i], w1[(k * KH_ + kh) * I_ + i], s);
        g_A1[r] = s;
    }
}

__global__ __launch_bounds__(NTH, 2)
void fused_h16b(const float* __restrict__ x, float* __restrict__ out) {
    extern __shared__ char sm[];
    uint32_t* xs    = (uint32_t*)(sm + OFF_XS);     // [ms][col(121)][j2(12)] half2
    uint32_t* Cs    = (uint32_t*)(sm + OFF_CS);     // [kq2][k] half2
    float*    xedge = (float*)(sm + OFF_XEDGE);     // [ms][j][9] fp32 edge cols
    float*    corrP = (float*)(sm + OFF_CORRP);     // [ms][k][kh]
    float*    corr  = (float*)(sm + OFF_CORR);      // [ms][k]

    const int t    = threadIdx.x;
    const int lane = t & 31;
    const int wid  = t >> 5;
    const int l    = blockIdx.x / 14;
    const int m0   = (blockIdx.x % 14) * MT;

    // ---- staging ----
    // combined weights -> smem (coalesced uint4)
    {
        const uint4* s4 = (const uint4*)g_Ch;
        uint4*       d4 = (uint4*)Cs;
        for (int idx = t; idx < ((NKQ / 2) * KO_) / 4; idx += NTH) d4[idx] = s4[idx];
    }
    // zero pad cols 0..4 and 117..120
    for (int idx = t; idx < MT * 9 * 12; idx += NTH) {
        int ms = idx / 108, r = idx % 108;
        int c9 = r / 12, j2 = r % 12;
        int col = (c9 < 5) ? c9 : (112 + c9);
        xs[ms * XW + col * 12 + j2] = 0u;
    }
    // x -> transposed half2 smem; capture fp32 edges
    for (int idx = t; idx < MT * 12 * 28; idx += NTH) {
        int j2 = idx % 12;
        int cq = (idx / 12) % 28;
        int ms = idx / (12 * 28);
        int j  = 2 * j2;
        const float* xr = x + (((size_t)l * J_ + j) * NPIX + (m0 + ms)) * NPIX + 4 * cq;
        float4 g0 = *(const float4*)xr;
        float4 g1 = *(const float4*)(xr + NPIX * NPIX);
        float a0[4] = {g0.x, g0.y, g0.z, g0.w};
        float a1[4] = {g1.x, g1.y, g1.z, g1.w};
        #pragma unroll
        for (int c = 0; c < 4; c++) {
            int h = 4 * cq + c;
            __half2 hv = __floats2half2_rn(a0[c], a1[c]);
            xs[ms * XW + (h + 5) * 12 + j2] = *(uint32_t*)&hv;
            if (h < 4) {
                xedge[(ms * J_ + j) * 9 + h] = a0[c];
                xedge[(ms * J_ + j + 1) * 9 + h] = a1[c];
            } else if (h >= 107) {
                xedge[(ms * J_ + j) * 9 + h - 103] = a0[c];
                xedge[(ms * J_ + j + 1) * 9 + h - 103] = a1[c];
            }
        }
    }
    __syncthreads();

    // ---- corr partials: corrP[ms][k][kh] (n==0 cyclic-wrap fix) ----
    for (int e = t; e < MT * KO_ * KH_; e += NTH) {
        int ms  = e / (KO_ * KH_);
        int rem = e % (KO_ * KH_);
        int k   = rem / KH_, kh = rem % KH_;
        int   eidx = (kh <= 4) ? (4 + kh) : (kh - 5);
        float sgn  = (kh <= 4) ? 1.0f : -1.0f;
        const float* a1r = g_A1 + (k * KH_ + kh) * J_;
        float s = 0.0f;
        #pragma unroll
        for (int j = 0; j < J_; j++)
            s = fmaf(xedge[(ms * J_ + j) * 9 + eidx], a1r[j], s);
        corrP[e] = sgn * s;
    }
    __syncthreads();

    // reduction (192 threads; other warps proceed to GEMM)
    if (t < MT * KO_) {
        float c = 0.0f;
        #pragma unroll
        for (int kh = 0; kh < KH_; kh++) c += corrP[t * KH_ + kh];
        corr[t] = c;
    }

    // ---- fp16 GEMM: D[112,24] per m-row; 4 row-tiles per warp share B ----
    const int qa = lane & 3;
    const int ua = lane >> 2;
    int xoff[4];
    #pragma unroll
    for (int tt = 0; tt < 4; tt++) {
        int g = wid * 4 + tt;            // 0..55
        xoff[tt] = (g / 7) * XW + ((g % 7) * 16 + ua) * 12 + qa;
    }
    const uint32_t* pB = Cs + qa * KO_ + ua;

    float acc[4][3][4];
    #pragma unroll
    for (int a = 0; a < 4; a++)
        #pragma unroll
        for (int b = 0; b < 3; b++)
            #pragma unroll
            for (int c = 0; c < 4; c++) acc[a][b][c] = 0.0f;

    #pragma unroll
    for (int ks = 0; ks < 15; ks++) {
        uint32_t bf[3][2];
        #pragma unroll
        for (int nt = 0; nt < 3; nt++) {
            bf[nt][0] = pB[192 * ks + nt * 8];        // kq2 = 8ks+qa
            bf[nt][1] = pB[192 * ks + nt * 8 + 96];   // kq2 + 4
        }
        #pragma unroll
        for (int tt = 0; tt < 4; tt++) {
            const uint32_t* xa = xs + xoff[tt] + 8 * ks;
            uint32_t af[4];
            af[0] = xa[0];       // row p,   kq = 16ks+2qa
            af[1] = xa[96];      // row p+8
            af[2] = xa[4];       // row p,   kq+8
            af[3] = xa[100];     // row p+8, kq+8
            #pragma unroll
            for (int nt = 0; nt < 3; nt++)
                mma_f16(acc[tt][nt], af, bf[nt]);
        }
    }
    __syncthreads();   // corr visibility

    // ---- epilogue (32B-sector coalesced STG.32) ----
    #pragma unroll
    for (int tt = 0; tt < 4; tt++) {
        const int g  = wid * 4 + tt;
        const int ms = g / 7;
        const int rt = g % 7;
        const int m  = m0 + ms;
        const int p  = rt * 16 + ua;
        const bool edge = (rt == 0 && ua == 0);   // p == 0
        #pragma unroll
        for (int nt = 0; nt < 3; nt++) {
            const int k0 = nt * 8 + 2 * qa;
            float c0 = acc[tt][nt][0], c1 = acc[tt][nt][1];
            float c2 = acc[tt][nt][2], c3 = acc[tt][nt][3];
            if (edge) {
                c0 += corr[ms * KO_ + k0];
                c1 += corr[ms * KO_ + k0 + 1];
            }
            float* o0 = out + (((size_t)l * KO_ + k0) * NPIX + m) * NPIX + p;
            float* o1 = out + (((size_t)l * KO_ + k0 + 1) * NPIX + m) * NPIX + p;
            o0[0] = c0;
            o1[0] = c1;
            o0[8] = c2;
            o1[8] = c3;
        }
    }
}

extern "C" void kernel_launch(void* const* d_in, const int* in_sizes, int n_in,
                              void* d_out, int out_size) {
    const float* x  = (const float*)d_in[0];
    const float* w1 = (const float*)d_in[1];
    const float* w2 = (const float*)d_in[2];
    if (n_in >= 3 && in_sizes[1] == 672 && in_sizes[2] == 3024) {
        const float* tmp = w1; w1 = w2; w2 = tmp;
    }
    float* out = (float*)d_out;

    prologue_kernel<<<32, 256>>>(w1, w2);

    cudaFuncSetAttribute(fused_h16b,
                         cudaFuncAttributeMaxDynamicSharedMemorySize, SMEM_SZ);
    fused_h16b<<<L_ * 14, NTH, SMEM_SZ>>>(x, out);
}

// round 12
// speedup vs baseline: 1.0920x; 1.0920x over previous
#include <cuda_runtime.h>
#include <cuda_fp16.h>
#include <cstdint>

#define L_    128
#define J_    24
#define NPIX  112
#define I_    14
#define KH_   9
#define KO_   24
#define MT    4
#define NTH   448
#define NKQ   240            // K' = 10 taps * 24 j
#define XW    1452           // xs words per ms slice: 121 cols * 12 half2-words

// Precomputed combined weights (prologue output)
__device__ uint32_t g_Ch[(NKQ / 2) * KO_];   // half2 {C[2q][k], C[2q+1][k]}
__device__ float    g_A1[KO_ * KH_ * J_];    // fp32 [k][kh][j] (n==0 wrap fix)

__device__ __forceinline__ void mma_f16(float* d, const uint32_t* a, const uint32_t* b) {
    asm volatile(
        "mma.sync.aligned.m16n8k16.row.col.f32.f16.f16.f32 "
        "{%0,%1,%2,%3}, {%4,%5,%6,%7}, {%8,%9}, {%0,%1,%2,%3};"
        : "+f"(d[0]), "+f"(d[1]), "+f"(d[2]), "+f"(d[3])
        : "r"(a[0]), "r"(a[1]), "r"(a[2]), "r"(a[3]), "r"(b[0]), "r"(b[1]));
}

__device__ __forceinline__ void ldsm_x4(uint32_t* r, uint32_t saddr) {
    asm volatile(
        "ldmatrix.sync.aligned.m8n8.x4.shared.b16 {%0,%1,%2,%3}, [%4];"
        : "=r"(r[0]), "=r"(r[1]), "=r"(r[2]), "=r"(r[3])
        : "r"(saddr));
}

__device__ __forceinline__ uint32_t smem_u32(const void* p) {
    uint32_t a;
    asm("{ .reg .u64 t; cvta.to.shared.u64 t, %1; cvt.u32.u64 %0, t; }" : "=r"(a) : "l"(p));
    return a;
}

__device__ __forceinline__ float cval(const float* __restrict__ w1,
                                      const float* __restrict__ w2,
                                      int kq, int k) {
    int t10 = kq / J_, j = kq % J_;
    float c = 0.0f;
    if (t10 >= 1) {
        int kh = t10 - 1;
        #pragma unroll
        for (int i = 0; i < I_; i++)
            c = fmaf(w2[(j * 2 + 0) * I_ + i], w1[(k * KH_ + kh) * I_ + i], c);
    }
    if (t10 <= 8) {
        int kh = t10;
        #pragma unroll
        for (int i = 0; i < I_; i++)
            c = fmaf(w2[(j * 2 + 1) * I_ + i], w1[(k * KH_ + kh) * I_ + i], c);
    }
    return c;
}

__global__ void prologue_kernel(const float* __restrict__ w1,
                                const float* __restrict__ w2) {
    int idx = blockIdx.x * blockDim.x + threadIdx.x;
    if (idx < (NKQ / 2) * KO_) {
        int kq2 = idx / KO_, k = idx % KO_;
        float c0 = cval(w1, w2, 2 * kq2, k);
        float c1 = cval(w1, w2, 2 * kq2 + 1, k);
        __half2 h = __floats2half2_rn(c0, c1);   // low = even kq
        g_Ch[idx] = *(uint32_t*)&h;
    } else if (idx < (NKQ / 2) * KO_ + KO_ * KH_ * J_) {
        int r = idx - (NKQ / 2) * KO_;
        int k = r / (KH_ * J_);
        int rem = r % (KH_ * J_);
        int kh = rem / J_, j = rem % J_;
        float s = 0.0f;
        #pragma unroll
        for (int i = 0; i < I_; i++)
            s = fmaf(w2[(j * 2 + 1) * I_ + i], w1[(k * KH_ + kh) * I_ + i], s);
        g_A1[r] = s;
    }
}

__global__ __launch_bounds__(NTH, 2)
void fused_h16m(const float* __restrict__ x, float* __restrict__ out) {
    __shared__ uint32_t xs[MT * XW];         // [ms][col(121)][j2(12)] half2   23,232 B
    __shared__ uint32_t Cs[(NKQ / 2) * KO_]; // [kq2][k] half2                 11,520 B
    __shared__ float xedge[MT][J_][9];       // fp32 edge cols                  3,456 B
    __shared__ float corrP[MT][KO_][KH_];    //                                 3,456 B
    __shared__ float corr[MT][KO_];          //                                   384 B

    const int t    = threadIdx.x;
    const int lane = t & 31;
    const int wid  = t >> 5;
    const int l    = blockIdx.x / 28;
    const int m0   = (blockIdx.x % 28) * MT;

    // ---- staging ----
    {
        const uint4* s4 = (const uint4*)g_Ch;
        uint4*       d4 = (uint4*)Cs;
        for (int idx = t; idx < ((NKQ / 2) * KO_) / 4; idx += NTH) d4[idx] = s4[idx];
    }
    // zero pad cols 0..4 and 117..120
    for (int idx = t; idx < MT * 9 * 12; idx += NTH) {
        int ms = idx / 108, r = idx % 108;
        int c9 = r / 12, j2 = r % 12;
        int col = (c9 < 5) ? c9 : (112 + c9);
        xs[ms * XW + col * 12 + j2] = 0u;
    }
    // x -> transposed half2 smem; capture fp32 edges
    for (int idx = t; idx < MT * 12 * 28; idx += NTH) {
        int j2 = idx % 12;
        int cq = (idx / 12) % 28;
        int ms = idx / (12 * 28);
        int j  = 2 * j2;
        const float* xr = x + (((size_t)l * J_ + j) * NPIX + (m0 + ms)) * NPIX + 4 * cq;
        float4 g0 = *(const float4*)xr;
        float4 g1 = *(const float4*)(xr + NPIX * NPIX);
        float a0[4] = {g0.x, g0.y, g0.z, g0.w};
        float a1[4] = {g1.x, g1.y, g1.z, g1.w};
        #pragma unroll
        for (int c = 0; c < 4; c++) {
            int h = 4 * cq + c;
            __half2 hv = __floats2half2_rn(a0[c], a1[c]);
            xs[ms * XW + (h + 5) * 12 + j2] = *(uint32_t*)&hv;
            if (h < 4) {
                xedge[ms][j][h] = a0[c];
                xedge[ms][j + 1][h] = a1[c];
            } else if (h >= 107) {
                xedge[ms][j][h - 103] = a0[c];
                xedge[ms][j + 1][h - 103] = a1[c];
            }
        }
    }
    __syncthreads();

    // ---- corr partials (n==0 cyclic-wrap fix) ----
    for (int e = t; e < MT * KO_ * KH_; e += NTH) {
        int ms  = e / (KO_ * KH_);
        int rem = e % (KO_ * KH_);
        int k   = rem / KH_, kh = rem % KH_;
        int   eidx = (kh <= 4) ? (4 + kh) : (kh - 5);
        float sgn  = (kh <= 4) ? 1.0f : -1.0f;
        const float* a1r = g_A1 + (k * KH_ + kh) * J_;
        float s = 0.0f;
        #pragma unroll
        for (int j = 0; j < J_; j++)
            s = fmaf(xedge[ms][j][eidx], a1r[j], s);
        corrP[ms][k][kh] = sgn * s;
    }
    __syncthreads();

    if (t < MT * KO_) {
        int ms = t / KO_, k = t % KO_;
        float c = 0.0f;
        #pragma unroll
        for (int kh = 0; kh < KH_; kh++) c += corrP[ms][k][kh];
        corr[ms][k] = c;
    }

    // ---- fp16 GEMM via ldmatrix: D[112,24] per m-row, 2 row-tiles/warp ----
    const int qa = lane & 3;
    const int ua = lane >> 2;
    int msT[2], rtT[2];
    #pragma unroll
    for (int tt = 0; tt < 2; tt++) {
        int g = wid * 2 + tt;            // 0..27
        msT[tt] = g / 7;
        rtT[tt] = g % 7;
    }
    // ldmatrix per-lane row address: lanes 0..15 -> rows p0+ (lane&15), chunk 0;
    //                                lanes 16..31 -> same rows, chunk +16B (kq2+4)
    const uint32_t xs_s = smem_u32(xs);
    uint32_t xaddr[2];
    #pragma unroll
    for (int tt = 0; tt < 2; tt++) {
        int p_row = rtT[tt] * 16 + (lane & 15);
        xaddr[tt] = xs_s + (uint32_t)(msT[tt] * XW + p_row * 12) * 4u + (uint32_t)((lane >> 4) * 16);
    }
    const uint32_t* pB = Cs + qa * KO_ + ua;

    float acc[2][3][4];
    #pragma unroll
    for (int a = 0; a < 2; a++)
        #pragma unroll
        for (int b = 0; b < 3; b++)
            #pragma unroll
            for (int c = 0; c < 4; c++) acc[a][b][c] = 0.0f;

    #pragma unroll
    for (int ks = 0; ks < 15; ks++) {
        uint32_t bf[3][2];
        #pragma unroll
        for (int nt = 0; nt < 3; nt++) {
            bf[nt][0] = pB[192 * ks + nt * 8];        // kq2 = 8ks+qa
            bf[nt][1] = pB[192 * ks + nt * 8 + 96];   // kq2 + 4
        }
        #pragma unroll
        for (int tt = 0; tt < 2; tt++) {
            uint32_t af[4];
            ldsm_x4(af, xaddr[tt] + 32u * ks);        // a0,a1,a2,a3 fragment
            #pragma unroll
            for (int nt = 0; nt < 3; nt++)
                mma_f16(acc[tt][nt], af, bf[nt]);
        }
    }
    __syncthreads();   // corr visibility

    // ---- epilogue ----
    #pragma unroll
    for (int tt = 0; tt < 2; tt++) {
        const int m = m0 + msT[tt];
        const int p = rtT[tt] * 16 + ua;
        const bool edge = (rtT[tt] == 0 && ua == 0);   // p == 0
        #pragma unroll
        for (int nt = 0; nt < 3; nt++) {
            const int k0 = nt * 8 + 2 * qa;
            float c0 = acc[tt][nt][0], c1 = acc[tt][nt][1];
            float c2 = acc[tt][nt][2], c3 = acc[tt][nt][3];
            if (edge) {
                c0 += corr[msT[tt]][k0];
                c1 += corr[msT[tt]][k0 + 1];
            }
            float* o0 = out + (((size_t)l * KO_ + k0) * NPIX + m) * NPIX + p;
            float* o1 = out + (((size_t)l * KO_ + k0 + 1) * NPIX + m) * NPIX + p;
            o0[0] = c0;
            o1[0] = c1;
            o0[8] = c2;
            o1[8] = c3;
        }
    }
}

extern "C" void kernel_launch(void* const* d_in, const int* in_sizes, int n_in,
                              void* d_out, int out_size) {
    const float* x  = (const float*)d_in[0];
    const float* w1 = (const float*)d_in[1];
    const float* w2 = (const float*)d_in[2];
    if (n_in >= 3 && in_sizes[1] == 672 && in_sizes[2] == 3024) {
        const float* tmp = w1; w1 = w2; w2 = tmp;
    }
    float* out = (float*)d_out;

    prologue_kernel<<<32, 256>>>(w1, w2);
    fused_h16m<<<L_ * 28, NTH>>>(x, out);
}